// round 10
// baseline (speedup 1.0000x reference)
#include <cuda_runtime.h>
#include <math.h>

#define K_CB 196560
#define EMB 24
#define TPB 320          // threads per block (10 warps)
#define TPW 4            // tokens per warp (register-resident)
#define TB  40           // tokens per block = 10 * 4
#define CH  160          // codebook rows per smem chunk
#define NBARS_TOTAL 22

// ---------------- device scratch (static allocation only) ----------------
__device__ float g_res[12288];                   // residual [2][24][16][16]
__device__ float g_rdown[512 * EMB];             // downsampled tokens [N][24]
__device__ float g_zq[512 * EMB];                // quantized tokens (post-STE)
__device__ unsigned long long g_bestbuf[2][512]; // double-buffered (sim,~idx)
__device__ float g_wd[10][16][16];               // down weights
__device__ float g_wu[10][16][16];               // up weights
__device__ int g_barcnt;                         // grid barrier arrivals
__device__ int g_bargen;                         // grid barrier generation

__constant__ int c_hs[10] = {1, 2, 3, 4, 5, 6, 8, 10, 13, 16};

// ---------------- helpers ----------------
__device__ __forceinline__ unsigned int forder(float f) {
    unsigned int u = __float_as_uint(f);
    return (u & 0x80000000u) ? ~u : (u | 0x80000000u);
}
__device__ __forceinline__ unsigned long long ffma2(unsigned long long a,
                                                    unsigned long long b,
                                                    unsigned long long c) {
    unsigned long long d;
    asm("fma.rn.f32x2 %0, %1, %2, %3;" : "=l"(d) : "l"(a), "l"(b), "l"(c));
    return d;
}
__device__ __forceinline__ float2 unpackf2(unsigned long long v) {
    float lo, hi;
    asm("mov.b64 {%0, %1}, %2;" : "=f"(lo), "=f"(hi) : "l"(v));
    return make_float2(lo, hi);
}

// jax.image.resize compute_weight_mat (triangle kernel, antialias, tr=0)
__device__ void compute_col(int in_size, int out_size, int o, float* wcol) {
    float inv_scale = (float)((double)in_size / (double)out_size);
    float kscale = fmaxf(inv_scale, 1.0f);
    float sample_f = ((float)o + 0.5f) * inv_scale - 0.5f;
    float total = 0.0f;
    for (int i = 0; i < in_size; ++i) {
        float x = fabsf(sample_f - (float)i) / kscale;
        float w = fmaxf(0.0f, 1.0f - x);
        wcol[i] = w;
        total += w;
    }
    bool ok = fabsf(total) > 1000.0f * 1.1920928955078125e-7f;
    float denom = (total != 0.0f) ? total : 1.0f;
    bool inr = (sample_f >= -0.5f) && (sample_f <= (float)in_size - 0.5f);
    for (int i = 0; i < in_size; ++i) {
        float w = ok ? (wcol[i] / denom) : 0.0f;
        wcol[i] = inr ? w : 0.0f;
    }
}

// generation-counter grid barrier; gen is a per-thread local tracker
__device__ __forceinline__ void grid_barrier(int& gen) {
    __syncthreads();
    if (threadIdx.x == 0) {
        __threadfence();
        if (atomicAdd(&g_barcnt, 1) == (int)gridDim.x - 1) {
            atomicExch(&g_barcnt, 0);
            __threadfence();
            atomicAdd(&g_bargen, 1);
        } else {
            while (atomicAdd(&g_bargen, 0) < gen + 1) __nanosleep(64);
        }
        __threadfence();
    }
    gen++;
    __syncthreads();
}

// exact per-(row,token) dot order used since R5 (do not reorder)
#define ROW_DOT(acc, zz)                                     \
    do {                                                     \
        acc = ffma2(q0.x, zz[0].x, 0ull);                    \
        acc = ffma2(q0.y, zz[0].y, acc);                     \
        acc = ffma2(q1.x, zz[1].x, acc);                     \
        acc = ffma2(q1.y, zz[1].y, acc);                     \
        acc = ffma2(q2.x, zz[2].x, acc);                     \
        acc = ffma2(q2.y, zz[2].y, acc);                     \
        acc = ffma2(q3.x, zz[3].x, acc);                     \
        acc = ffma2(q3.y, zz[3].y, acc);                     \
        acc = ffma2(q4.x, zz[4].x, acc);                     \
        acc = ffma2(q4.y, zz[4].y, acc);                     \
        acc = ffma2(q5.x, zz[5].x, acc);                     \
        acc = ffma2(q5.y, zz[5].y, acc);                     \
    } while (0)

// ---------------- the whole algorithm in one persistent kernel -----------
__global__ void __launch_bounds__(TPB, 1)
fused_kernel(const float* __restrict__ z, const float* __restrict__ cb,
             float* __restrict__ out) {
    // row chunks: 112B-padded rows (7 ulonglong2 slots, slot 6 = pad)
    __shared__ __align__(16) ulonglong2 s_rows[2][CH * 7];
    __shared__ float s_a[16][16];
    __shared__ float s_b[16][16];
    __shared__ float s_c[16][16];
    __shared__ int s_base;

    int tid = threadIdx.x;
    int blk = blockIdx.x;
    int NB = gridDim.x;

    // per-run barrier base (replay-safe: g_bargen advances exactly
    // NBARS_TOTAL per run; all entry reads happen before first release)
    if (tid == 0) {
        int g = atomicAdd(&g_bargen, 0);
        s_base = (g / NBARS_TOTAL) * NBARS_TOTAL;
    }
    __syncthreads();
    int gen = s_base;

    // ---- phase 0: copy residual, zero z_hat, weights, zero best bufs ----
    if (blk < 48) {
        for (int i = tid; i < 256; i += TPB) {
            g_res[blk * 256 + i] = z[blk * 256 + i];
            out[blk * 256 + i] = 0.0f;
        }
        if (blk == 0) {
            for (int i = tid; i < 1024; i += TPB)
                ((unsigned long long*)g_bestbuf)[i] = 0ull;
        }
    } else if (blk < 148) {
        if (tid == 0) {
            const int hs9[9] = {1, 2, 3, 4, 5, 6, 8, 10, 13};
            for (int j = 0; j < 2; j++) {
                int task = (blk - 48) * 2 + j;
                if (task >= 196) break;
                float wcol[16];
                if (task < 52) {
                    int rem = task, s = 0;
                    while (rem >= hs9[s]) { rem -= hs9[s]; s++; }
                    compute_col(16, hs9[s], rem, wcol);
                    for (int i = 0; i < 16; i++) g_wd[s][i][rem] = wcol[i];
                } else {
                    int r = task - 52;
                    int s = r / 16, o = r % 16;
                    compute_col(hs9[s], 16, o, wcol);
                    for (int i = 0; i < 16; i++)
                        g_wu[s][i][o] = (i < hs9[s]) ? wcol[i] : 0.0f;
                }
            }
        }
    }
    grid_barrier(gen);

    // ---- scale-0 downsample (h=1), blocks 0..47, one (b,d) plane each ---
    if (blk < 48) {
        int b = blk / 24, d = blk % 24;
        for (int i = tid; i < 256; i += TPB)
            s_a[i >> 4][i & 15] = g_res[blk * 256 + i];
        __syncthreads();
        if (tid < 16) {
            float acc = 0.0f;
            for (int Y = 0; Y < 16; Y++) acc += g_wd[0][Y][0] * s_a[Y][tid];
            s_b[0][tid] = acc;
        }
        __syncthreads();
        if (tid == 0) {
            float acc = 0.0f;
            for (int X = 0; X < 16; X++) acc += g_wd[0][X][0] * s_b[0][X];
            g_rdown[b * EMB + d] = acc;
        }
    }
    grid_barrier(gen);

    // each thread owns 3 of the 960 16B-vectors per chunk (constant map)
    int ld_rr[3], ld_k[3];
#pragma unroll
    for (int j = 0; j < 3; j++) {
        int v = tid * 3 + j;
        ld_rr[j] = v / 6;
        ld_k[j] = v % 6;
    }

    // ---- 10 scales ----
    int off = 12288;
    for (int s = 0; s < 10; s++) {
        int h = c_hs[s];
        int N = 2 * h * h;
        int tiles = (N + TB - 1) / TB;
        int nsl = NB / tiles;
        int tile = blk % tiles;
        int slice = blk / tiles;
        unsigned long long* best = g_bestbuf[s & 1];

        // ======= scan: tokens in regs, rows chunk-streamed via smem ======
        if (slice < nsl) {
            int warp = tid >> 5, lane = tid & 31;
            int tokbase = tile * TB + warp * TPW;

            ulonglong2 zt[TPW][6];
#pragma unroll
            for (int j = 0; j < TPW; j++) {
                int tk = tokbase + j;
                if (tk < N) {
                    const ulonglong2* tz =
                        (const ulonglong2*)(g_rdown + (size_t)tk * EMB);
#pragma unroll
                    for (int k = 0; k < 6; k++) zt[j][k] = __ldcg(tz + k);
                } else {
#pragma unroll
                    for (int k = 0; k < 6; k++)
                        zt[j][k] = make_ulonglong2(0ull, 0ull);
                }
            }

            float bestv[TPW];
            int besti[TPW];
#pragma unroll
            for (int j = 0; j < TPW; j++) { bestv[j] = -3.4e38f; besti[j] = 0; }

            int rpb = (K_CB + nsl - 1) / nsl;
            int rbeg = slice * rpb;
            int rend = min(K_CB, rbeg + rpb);
            const ulonglong2* __restrict__ cbu = (const ulonglong2*)cb;

            // prologue: load chunk 0 into buffer 0
            ulonglong2 pre[3];
#pragma unroll
            for (int j = 0; j < 3; j++) {
                int gr = rbeg + ld_rr[j];
                pre[j] = (gr < rend) ? __ldg(cbu + (size_t)gr * 6 + ld_k[j])
                                     : make_ulonglong2(0ull, 0ull);
            }
#pragma unroll
            for (int j = 0; j < 3; j++)
                s_rows[0][ld_rr[j] * 7 + ld_k[j]] = pre[j];
            __syncthreads();

            for (int rbase = rbeg, buf = 0; rbase < rend;
                 rbase += CH, buf ^= 1) {
                int cnt = min(CH, rend - rbase);
                int nbase = rbase + CH;
                bool more = nbase < rend;
                // issue next-chunk loads first (latency hides under compute)
                if (more) {
#pragma unroll
                    for (int j = 0; j < 3; j++) {
                        int gr = nbase + ld_rr[j];
                        pre[j] = (gr < rend)
                                     ? __ldg(cbu + (size_t)gr * 6 + ld_k[j])
                                     : make_ulonglong2(0ull, 0ull);
                    }
                }
                // compute: every warp scans all cnt rows for its own tokens
                const ulonglong2* sb = s_rows[buf];
                for (int rr = lane; rr < cnt; rr += 32) {
                    const ulonglong2* rp = sb + rr * 7;
                    ulonglong2 q0 = rp[0], q1 = rp[1], q2 = rp[2];
                    ulonglong2 q3 = rp[3], q4 = rp[4], q5 = rp[5];
                    unsigned long long a0, a1, a2, a3;
                    ROW_DOT(a0, zt[0]);
                    ROW_DOT(a1, zt[1]);
                    ROW_DOT(a2, zt[2]);
                    ROW_DOT(a3, zt[3]);
                    float2 f0 = unpackf2(a0), f1 = unpackf2(a1);
                    float2 f2 = unpackf2(a2), f3 = unpackf2(a3);
                    float s0 = f0.x + f0.y;
                    float s1 = f1.x + f1.y;
                    float s2 = f2.x + f2.y;
                    float s3 = f3.x + f3.y;
                    int r = rbase + rr;
                    if (s0 > bestv[0]) { bestv[0] = s0; besti[0] = r; }
                    if (s1 > bestv[1]) { bestv[1] = s1; besti[1] = r; }
                    if (s2 > bestv[2]) { bestv[2] = s2; besti[2] = r; }
                    if (s3 > bestv[3]) { bestv[3] = s3; besti[3] = r; }
                }
                if (more) {
#pragma unroll
                    for (int j = 0; j < 3; j++)
                        s_rows[buf ^ 1][ld_rr[j] * 7 + ld_k[j]] = pre[j];
                }
                __syncthreads();
            }

#pragma unroll
            for (int j = 0; j < TPW; j++) {
                unsigned long long pk =
                    ((unsigned long long)forder(bestv[j]) << 32) |
                    (unsigned long long)((unsigned)~besti[j]);
#pragma unroll
                for (int o2 = 16; o2; o2 >>= 1) {
                    unsigned long long o = __shfl_down_sync(0xFFFFFFFFu, pk, o2);
                    if (o > pk) pk = o;
                }
                if (lane == 0 && tokbase + j < N)
                    atomicMax(&best[tokbase + j], pk);
            }
        }
        grid_barrier(gen);

        // ============ finalize (redundant per block) + updown ============
        if (blk < 48) {
            // finalize all N tokens (identical values from every block)
            for (int n = tid; n < N; n += TPB) {
                unsigned long long pkv = __ldcg(&best[n]);
                unsigned row = ~((unsigned)(pkv & 0xFFFFFFFFull));
                out[off + n] = (float)row;
                const float* c = cb + (size_t)row * EMB;
                float ss = 0.0f;
                for (int d = 0; d < EMB; d++) { float v = c[d]; ss += v * v; }
                float nrm = sqrtf(ss);
                for (int d = 0; d < EMB; d++) {
                    float q = c[d] / nrm;
                    float zf = __ldcg(&g_rdown[n * EMB + d]);
                    g_zq[n * EMB + d] = zf + (q - zf);  // STE rounding
                }
            }
            __syncthreads();
            // updown own plane
            int b = blk / 24, d = blk % 24;
            for (int px = tid; px < h * h; px += TPB)
                s_a[px / h][px % h] = g_zq[(b * h * h + px) * EMB + d];
            __syncthreads();
            if (h == 16) {
                for (int px = tid; px < 256; px += TPB) {
                    float up = s_a[px >> 4][px & 15];
                    int g = blk * 256 + px;
                    out[g] += up;
                    float nr = g_res[g] - up;
                    g_res[g] = nr;
                    s_c[px >> 4][px & 15] = nr;
                }
            } else {
                for (int i = tid; i < 16 * h; i += TPB) {
                    int Y = i / h, x = i % h;
                    float acc = 0.0f;
                    for (int y = 0; y < h; y++) acc += g_wu[s][y][Y] * s_a[y][x];
                    s_b[Y][x] = acc;
                }
                __syncthreads();
                for (int px = tid; px < 256; px += TPB) {
                    int Y = px >> 4, X = px & 15;
                    float acc = 0.0f;
                    for (int x = 0; x < h; x++) acc += g_wu[s][x][X] * s_b[Y][x];
                    int g = blk * 256 + px;
                    out[g] += acc;
                    float nr = g_res[g] - acc;
                    g_res[g] = nr;
                    s_c[px >> 4][px & 15] = nr;
                }
            }
            __syncthreads();
            if (s < 9) {
                int hn = c_hs[s + 1];
                if (hn == 16) {  // jax resize skips equal dims -> identity
                    for (int px = tid; px < 256; px += TPB)
                        g_rdown[(b * 256 + px) * EMB + d] = s_c[px >> 4][px & 15];
                } else {
                    for (int i = tid; i < hn * 16; i += TPB) {
                        int y = i / 16, X = i % 16;
                        float acc = 0.0f;
                        for (int Y = 0; Y < 16; Y++)
                            acc += g_wd[s + 1][Y][y] * s_c[Y][X];
                        s_b[y][X] = acc;
                    }
                    __syncthreads();
                    for (int i = tid; i < hn * hn; i += TPB) {
                        int y = i / hn, x = i % hn;
                        float acc = 0.0f;
                        for (int X = 0; X < 16; X++)
                            acc += g_wd[s + 1][X][x] * s_b[y][X];
                        g_rdown[(b * hn * hn + i) * EMB + d] = acc;
                    }
                }
            }
        } else if (blk == 48 && s < 9) {
            unsigned long long* nxt = g_bestbuf[(s + 1) & 1];
            for (int n = tid; n < 512; n += TPB) nxt[n] = 0ull;
        }
        grid_barrier(gen);
        off += N;
    }
}

// ---------------- launch ---------------------------------------------------
extern "C" void kernel_launch(void* const* d_in, const int* in_sizes, int n_in,
                              void* d_out, int out_size) {
    const float* z;
    const float* cb;
    if (in_sizes[0] == 12288) {
        z = (const float*)d_in[0];
        cb = (const float*)d_in[1];
    } else {
        z = (const float*)d_in[1];
        cb = (const float*)d_in[0];
    }
    float* out = (float*)d_out;

    int dev = 0, nsm = 148;
    cudaGetDevice(&dev);
    cudaDeviceGetAttribute(&nsm, cudaDevAttrMultiProcessorCount, dev);

    fused_kernel<<<nsm, TPB>>>(z, cb, out);
}